// round 13
// baseline (speedup 1.0000x reference)
#include <cuda_runtime.h>
#include <cuda_fp16.h>
#include <math.h>
#include <stdint.h>

#define KDIM 1024
#define NH   4096
#define NTOT 8192
#define BM   128                                 // tile rows
#define BN   64                                  // tile cols
#define NROWT (NTOT / BM)                        // 64
#define NBLOCKS (NROWT * (NROWT + 1))            // 4160 tiles: i(i+1)+j, j<2i+2
#define CHUNK 64                                 // K elements per stage (128 bytes)
#define NCHUNK (KDIM / CHUNK)                    // 16
#define NST 2
#define A_TILE_BYTES (BM * 128)                  // 16 KB
#define B_TILE_BYTES (BN * 128)                  // 8 KB
#define STAGE_BYTES (A_TILE_BYTES + B_TILE_BYTES)// 24 KB
#define DYN_BYTES (NST * STAGE_BYTES + 256)      // ~48.25 KB

#define PRE_BLOCKS 256

// ---------------- device scratch ----------------
__device__ float  g_sq[NTOT];
__device__ float  g_colpart_blk[PRE_BLOCKS][KDIM];
__device__ double g_sumsq_blk[PRE_BLOCKS];
__device__ float  g_coef;       // -1 / (16 * bandwidth)
__device__ double g_accum;
__device__ unsigned g_prectr = 0;    // self-resetting tickets
__device__ unsigned g_donectr = 0;
__device__ __half g_total[(size_t)NTOT * KDIM];  // f16 copy of [S;T]

// ---------------- PTX helpers (plain sm_80+ PTX) ----------------
__device__ __forceinline__ uint32_t smem_u32(const void* p) {
  uint32_t a;
  asm("{ .reg .u64 t; cvta.to.shared.u64 t, %1; cvt.u32.u64 %0, t; }" : "=r"(a) : "l"(p));
  return a;
}
__device__ __forceinline__ void cp16(uint32_t dst, const void* src) {
  asm volatile("cp.async.cg.shared.global [%0], [%1], 16;" :: "r"(dst), "l"(src) : "memory");
}
__device__ __forceinline__ void cp_commit() {
  asm volatile("cp.async.commit_group;" ::: "memory");
}
template <int N>
__device__ __forceinline__ void cp_wait() {
  asm volatile("cp.async.wait_group %0;" :: "n"(N) : "memory");
}
__device__ __forceinline__ void ldsm4(uint32_t* r, uint32_t addr) {
  asm volatile("ldmatrix.sync.aligned.m8n8.x4.shared.b16 {%0,%1,%2,%3}, [%4];"
               : "=r"(r[0]), "=r"(r[1]), "=r"(r[2]), "=r"(r[3]) : "r"(addr));
}
// f16 x f16 -> f16 accumulate (2 c-regs = 4 packed halves)
__device__ __forceinline__ void mma16816h(uint32_t* c, const uint32_t* a,
                                          uint32_t b0, uint32_t b1) {
  asm volatile(
    "mma.sync.aligned.m16n8k16.row.col.f16.f16.f16.f16 "
    "{%0,%1}, {%2,%3,%4,%5}, {%6,%7}, {%0,%1};"
    : "+r"(c[0]), "+r"(c[1])
    : "r"(a[0]), "r"(a[1]), "r"(a[2]), "r"(a[3]), "r"(b0), "r"(b1));
}

// ---------------- fused preprocessing + bandwidth (last block) ----------------
__global__ void __launch_bounds__(256)
k_pre(const float* __restrict__ S, const float* __restrict__ T) {
  __shared__ float  scol[KDIM];
  __shared__ double ssq[8];
  __shared__ double sred[256];
  __shared__ unsigned s_rank;

  const int tid  = threadIdx.x;
  const int wid  = tid >> 5;
  const int lane = tid & 31;

  if (blockIdx.x == 0 && tid == 0) g_accum = 0.0;

  #pragma unroll
  for (int i = 0; i < KDIM / 256; ++i) scol[tid + i * 256] = 0.f;
  __syncthreads();

  float4 colacc[8];
  #pragma unroll
  for (int i = 0; i < 8; ++i) colacc[i] = make_float4(0.f, 0.f, 0.f, 0.f);

  double wsumsq = 0.0;   // lane 0 accumulates full row norms

  #pragma unroll
  for (int r = 0; r < 4; ++r) {
    int row = blockIdx.x * 32 + wid * 4 + r;
    const float4* src = (const float4*)((row < NH) ? (S + (size_t)row * KDIM)
                                                   : (T + (size_t)(row - NH) * KDIM));
    float sq = 0.f;
    #pragma unroll
    for (int i = 0; i < 8; ++i) {
      float4 v = src[i * 32 + lane];
      sq += v.x * v.x + v.y * v.y + v.z * v.z + v.w * v.w;
      colacc[i].x += v.x; colacc[i].y += v.y;
      colacc[i].z += v.z; colacc[i].w += v.w;
      __half2 lo = __floats2half2_rn(v.x, v.y);
      __half2 hi = __floats2half2_rn(v.z, v.w);
      uint2 pk;
      pk.x = *(uint32_t*)&lo;
      pk.y = *(uint32_t*)&hi;
      *(uint2*)(g_total + (size_t)row * KDIM + i * 128 + lane * 4) = pk;
    }
    #pragma unroll
    for (int o = 16; o; o >>= 1) sq += __shfl_xor_sync(0xffffffffu, sq, o);
    if (lane == 0) g_sq[row] = sq;
    wsumsq += (double)sq;
  }

  #pragma unroll
  for (int i = 0; i < 8; ++i) {
    int c = i * 128 + lane * 4;
    atomicAdd(&scol[c + 0], colacc[i].x);
    atomicAdd(&scol[c + 1], colacc[i].y);
    atomicAdd(&scol[c + 2], colacc[i].z);
    atomicAdd(&scol[c + 3], colacc[i].w);
  }
  if (lane == 0) ssq[wid] = wsumsq;
  __syncthreads();

  #pragma unroll
  for (int i = 0; i < KDIM / 256; ++i) {
    int c = tid + i * 256;
    g_colpart_blk[blockIdx.x][c] = scol[c];
  }
  if (tid == 0) {
    double t = 0.0;
    #pragma unroll
    for (int i = 0; i < 8; ++i) t += ssq[i];
    g_sumsq_blk[blockIdx.x] = t;
  }

  // ---- last-block bandwidth reduction ----
  __threadfence();
  __syncthreads();
  if (tid == 0) s_rank = atomicAdd(&g_prectr, 1u);
  __syncthreads();
  if (s_rank != PRE_BLOCKS - 1) return;

  double csq = 0.0;
  #pragma unroll
  for (int i = 0; i < KDIM / 256; ++i) {
    int c = tid + i * 256;
    float s = 0.f;
    for (int b = 0; b < PRE_BLOCKS; ++b) s += g_colpart_blk[b][c];
    csq += (double)s * (double)s;
  }
  sred[tid] = csq;
  __syncthreads();
  for (int s = 128; s; s >>= 1) {
    if (tid < s) sred[tid] += sred[tid + s];
    __syncthreads();
  }
  double colsq = sred[0];
  __syncthreads();
  sred[tid] = g_sumsq_blk[tid];
  __syncthreads();
  for (int s = 128; s; s >>= 1) {
    if (tid < s) sred[tid] += sred[tid + s];
    __syncthreads();
  }
  if (tid == 0) {
    double sumsq = sred[0];
    double sumL2 = 2.0 * (double)NTOT * sumsq - 2.0 * colsq;
    double bw = sumL2 / ((double)NTOT * (double)NTOT - (double)NTOT);
    bw *= 0.25;
    g_coef = (float)(-1.0 / (16.0 * bw));
    g_prectr = 0;   // reset for next graph replay
  }
}

// ---------------- 128x64 tile via f16 mma.sync + fused epilogue + final ----------------
// SW128 swizzle on 128-byte rows: 16B-chunk index (bits [6:4]) XOR (row & 7).
__device__ __forceinline__ void load_stage(uint32_t sbase, const __half* Ab,
                                           const __half* Bb, int t, int tid) {
  #pragma unroll
  for (int i = 0; i < 4; ++i) {           // A: 1024 chunks
    int g   = tid + i * 256;
    int row = g >> 3;
    int cc  = g & 7;
    uint32_t soff = (uint32_t)row * 128u + (uint32_t)((cc ^ (row & 7)) << 4);
    cp16(sbase + soff, (const char*)(Ab + (size_t)row * KDIM + t * CHUNK) + cc * 16);
  }
  #pragma unroll
  for (int i = 0; i < 2; ++i) {           // B: 512 chunks
    int g   = tid + i * 256;
    int row = g >> 3;
    int cc  = g & 7;
    uint32_t soff = A_TILE_BYTES + (uint32_t)row * 128u + (uint32_t)((cc ^ (row & 7)) << 4);
    cp16(sbase + soff, (const char*)(Bb + (size_t)row * KDIM + t * CHUNK) + cc * 16);
  }
  cp_commit();
}

__global__ void __launch_bounds__(256, 4)
k_gemm(float* __restrict__ out) {
  extern __shared__ char dsm[];
  __shared__ double s_red[8];

  const int tid  = threadIdx.x;
  const int wid  = tid >> 5;
  const int lane = tid & 31;

  // tile decode: bid = i*(i+1) + j, j in [0, 2i+2)
  int bid = blockIdx.x;
  int bp = (int)((sqrtf(4.0f * (float)bid + 1.0f) - 1.0f) * 0.5f);
  while ((bp + 1) * (bp + 2) <= bid) ++bp;
  while (bp * (bp + 1) > bid) --bp;
  int bq = bid - bp * (bp + 1);
  const int rowBase = bp * BM;
  const int colBase = bq * BN;
  const bool straddle = ((bq >> 1) == bp);   // tile contains the diagonal

  const __half* Ab = g_total + (size_t)rowBase * KDIM;
  const __half* Bb = g_total + (size_t)colBase * KDIM;

  uint32_t sm0 = (smem_u32(dsm) + 127u) & ~127u;

  const int warp_m = wid & 3;    // 0..3 -> 32-row group
  const int warp_n = wid >> 2;   // 0..1 -> 32-col group
  const int lr  = lane & 7;
  const int sub = lane >> 3;

  uint32_t a_rowoff[2], a_rswz[2];
  #pragma unroll
  for (int mt = 0; mt < 2; ++mt) {
    int row = warp_m * 32 + mt * 16 + (sub & 1) * 8 + lr;
    a_rowoff[mt] = (uint32_t)row * 128u;
    a_rswz[mt]   = (uint32_t)(row & 7);
  }
  const uint32_t a_kbit = (uint32_t)(sub >> 1);

  uint32_t b_rowoff[2], b_rswz[2];
  #pragma unroll
  for (int np = 0; np < 2; ++np) {
    int row = warp_n * 32 + np * 16 + (sub >> 1) * 8 + lr;
    b_rowoff[np] = (uint32_t)row * 128u;
    b_rswz[np]   = (uint32_t)(row & 7);
  }
  const uint32_t b_kbit = (uint32_t)(sub & 1);

  uint32_t acc[2][4][2];   // f16x2 accumulators: 2 m-tiles x 4 n-tiles
  #pragma unroll
  for (int i = 0; i < 2; ++i)
    #pragma unroll
    for (int j = 0; j < 4; ++j) { acc[i][j][0] = 0u; acc[i][j][1] = 0u; }

  load_stage(sm0 + 0 * STAGE_BYTES, Ab, Bb, 0, tid);
  load_stage(sm0 + 1 * STAGE_BYTES, Ab, Bb, 1, tid);

  int st = 0;
  for (int t = 0; t < NCHUNK; ++t) {
    if (t == NCHUNK - 1) cp_wait<0>(); else cp_wait<1>();
    __syncthreads();

    uint32_t sA = sm0 + st * STAGE_BYTES;
    uint32_t sB = sA + A_TILE_BYTES;

    #pragma unroll
    for (int kk = 0; kk < 4; ++kk) {
      uint32_t kk2 = (uint32_t)(kk * 2);
      uint32_t af[2][4];
      #pragma unroll
      for (int mt = 0; mt < 2; ++mt)
        ldsm4(af[mt], sA + a_rowoff[mt] + (((kk2 + a_kbit) ^ a_rswz[mt]) << 4));
      uint32_t bf[2][4];
      #pragma unroll
      for (int np = 0; np < 2; ++np)
        ldsm4(bf[np], sB + b_rowoff[np] + (((kk2 + b_kbit) ^ b_rswz[np]) << 4));
      #pragma unroll
      for (int mt = 0; mt < 2; ++mt) {
        #pragma unroll
        for (int nt = 0; nt < 4; ++nt)
          mma16816h(acc[mt][nt], af[mt], bf[nt >> 1][(nt & 1) * 2],
                    bf[nt >> 1][(nt & 1) * 2 + 1]);
      }
    }

    __syncthreads();
    if (t + NST < NCHUNK) load_stage(sm0 + st * STAGE_BYTES, Ab, Bb, t + NST, tid);
    st ^= 1;
  }

  // ---- fused epilogue ----
  const float coef = g_coef;
  const int tg = lane >> 2;
  const int tc = lane & 3;

  float sqp[2][2], sqq[4][2];
  #pragma unroll
  for (int mt = 0; mt < 2; ++mt) {
    int p0 = rowBase + warp_m * 32 + mt * 16 + tg;
    sqp[mt][0] = g_sq[p0];
    sqp[mt][1] = g_sq[p0 + 8];
  }
  #pragma unroll
  for (int nt = 0; nt < 4; ++nt) {
    int q0 = colBase + warp_n * 32 + nt * 8 + tc * 2;
    sqq[nt][0] = g_sq[q0];
    sqq[nt][1] = g_sq[q0 + 1];
  }

  float fsum = 0.f;
  #pragma unroll
  for (int mt = 0; mt < 2; ++mt) {
    #pragma unroll
    for (int nt = 0; nt < 4; ++nt) {
      #pragma unroll
      for (int h = 0; h < 2; ++h) {          // h=0: row tg, h=1: row tg+8
        float2 f = __half22float2(*(const __half2*)&acc[mt][nt][h]);
        float L2a = sqp[mt][h] + sqq[nt][0] - 2.0f * f.x;
        float L2b = sqp[mt][h] + sqq[nt][1] - 2.0f * f.y;
        float va = __expf(L2a * coef);
        float vb = __expf(L2b * coef);
        float va2 = va * va, va4 = va2 * va2, va8 = va4 * va4;
        float vb2 = vb * vb, vb4 = vb2 * vb2, vb8 = vb4 * vb4;
        float ka = va + va2 + va4 + va8 + va8 * va8;
        float kb = vb + vb2 + vb4 + vb8 + vb8 * vb8;
        if (straddle) {
          int p  = rowBase + warp_m * 32 + mt * 16 + tg + h * 8;
          int qa = colBase + warp_n * 32 + nt * 8 + tc * 2;
          int qb = qa + 1;
          float wa = (qa < p) ? 2.f : ((qa == p) ? 1.f : 0.f);
          float wb = (qb < p) ? 2.f : ((qb == p) ? 1.f : 0.f);
          fsum += wa * ka + wb * kb;
        } else {
          fsum += ka + kb;
        }
      }
    }
  }
  double d = (double)fsum;
  #pragma unroll
  for (int o = 16; o; o >>= 1) d += __shfl_xor_sync(0xffffffffu, d, o);
  if (lane == 0) s_red[wid] = d;
  __syncthreads();
  if (tid == 0) {
    double t = 0.0;
    #pragma unroll
    for (int i = 0; i < 8; ++i) t += s_red[i];
    double sgn = ((rowBase < NH) == (colBase < NH)) ? 1.0 : -1.0;
    if (!straddle) sgn *= 2.0;   // strictly-below tiles count twice (symmetry)
    atomicAdd(&g_accum, sgn * t);

    // ---- fused finalization: last CTA writes the scalar output ----
    __threadfence();
    unsigned rank = atomicAdd(&g_donectr, 1u);
    if (rank == NBLOCKS - 1) {
      double total = atomicAdd(&g_accum, 0.0);   // ordered read after fence
      out[0] = (float)(total / ((double)NH * (double)NH));
      g_donectr = 0;   // reset for next graph replay
    }
  }
}

// ---------------- host launch ----------------
extern "C" void kernel_launch(void* const* d_in, const int* in_sizes, int n_in,
                              void* d_out, int out_size) {
  (void)in_sizes; (void)n_in; (void)out_size;
  const float* S = (const float*)d_in[0];
  const float* T = (const float*)d_in[1];

  cudaFuncSetAttribute(k_gemm, cudaFuncAttributeMaxDynamicSharedMemorySize, DYN_BYTES);

  k_pre<<<PRE_BLOCKS, 256>>>(S, T);
  k_gemm<<<NBLOCKS, 256, DYN_BYTES>>>((float*)d_out);
}

// round 14
// speedup vs baseline: 1.1028x; 1.1028x over previous
#include <cuda_runtime.h>
#include <cuda_fp16.h>
#include <math.h>
#include <stdint.h>

#define KDIM 1024
#define NH   4096
#define NTOT 8192
#define BM   128
#define NTILES (NTOT / BM)                       // 64
#define NBLOCKS (NTILES * (NTILES + 1) / 2)      // 2080
#define CHUNK 64                                 // K elements per stage (128 bytes)
#define NCHUNK (KDIM / CHUNK)                    // 16
#define NST 2
#define TILE_BYTES (BM * 128)                    // 16 KB
#define STAGE_BYTES (2 * TILE_BYTES)             // 32 KB
#define DYN_BYTES (NST * STAGE_BYTES + 256)      // ~64.25 KB

#define PRE_BLOCKS 256

// ---------------- device scratch ----------------
__device__ float  g_sq[NTOT];
__device__ float  g_colpart_blk[PRE_BLOCKS][KDIM];
__device__ double g_sumsq_blk[PRE_BLOCKS];
__device__ float  g_coef;       // -1 / (16 * bandwidth)
__device__ double g_accum;
__device__ unsigned g_prectr = 0;    // self-resetting tickets
__device__ unsigned g_donectr = 0;
__device__ __half g_total[(size_t)NTOT * KDIM];  // f16 copy of [S;T]

// ---------------- PTX helpers (plain sm_80+ PTX) ----------------
__device__ __forceinline__ uint32_t smem_u32(const void* p) {
  uint32_t a;
  asm("{ .reg .u64 t; cvta.to.shared.u64 t, %1; cvt.u32.u64 %0, t; }" : "=r"(a) : "l"(p));
  return a;
}
__device__ __forceinline__ void cp16(uint32_t dst, const void* src) {
  asm volatile("cp.async.cg.shared.global [%0], [%1], 16;" :: "r"(dst), "l"(src) : "memory");
}
__device__ __forceinline__ void cp_commit() {
  asm volatile("cp.async.commit_group;" ::: "memory");
}
template <int N>
__device__ __forceinline__ void cp_wait() {
  asm volatile("cp.async.wait_group %0;" :: "n"(N) : "memory");
}
__device__ __forceinline__ void ldsm4(uint32_t* r, uint32_t addr) {
  asm volatile("ldmatrix.sync.aligned.m8n8.x4.shared.b16 {%0,%1,%2,%3}, [%4];"
               : "=r"(r[0]), "=r"(r[1]), "=r"(r[2]), "=r"(r[3]) : "r"(addr));
}
// f16 x f16 -> f16 accumulate (2 c-regs = 4 packed halves)
__device__ __forceinline__ void mma16816h(uint32_t* c, const uint32_t* a,
                                          uint32_t b0, uint32_t b1) {
  asm volatile(
    "mma.sync.aligned.m16n8k16.row.col.f16.f16.f16.f16 "
    "{%0,%1}, {%2,%3,%4,%5}, {%6,%7}, {%0,%1};"
    : "+r"(c[0]), "+r"(c[1])
    : "r"(a[0]), "r"(a[1]), "r"(a[2]), "r"(a[3]), "r"(b0), "r"(b1));
}

// ---------------- fused preprocessing + bandwidth (last block) ----------------
__global__ void __launch_bounds__(256)
k_pre(const float* __restrict__ S, const float* __restrict__ T) {
  __shared__ float  scol[KDIM];
  __shared__ double ssq[8];
  __shared__ double sred[256];
  __shared__ unsigned s_rank;

  const int tid  = threadIdx.x;
  const int wid  = tid >> 5;
  const int lane = tid & 31;

  if (blockIdx.x == 0 && tid == 0) g_accum = 0.0;

  #pragma unroll
  for (int i = 0; i < KDIM / 256; ++i) scol[tid + i * 256] = 0.f;
  __syncthreads();

  float4 colacc[8];
  #pragma unroll
  for (int i = 0; i < 8; ++i) colacc[i] = make_float4(0.f, 0.f, 0.f, 0.f);

  double wsumsq = 0.0;   // lane 0 accumulates full row norms

  #pragma unroll
  for (int r = 0; r < 4; ++r) {
    int row = blockIdx.x * 32 + wid * 4 + r;
    const float4* src = (const float4*)((row < NH) ? (S + (size_t)row * KDIM)
                                                   : (T + (size_t)(row - NH) * KDIM));
    float sq = 0.f;
    #pragma unroll
    for (int i = 0; i < 8; ++i) {
      float4 v = src[i * 32 + lane];
      sq += v.x * v.x + v.y * v.y + v.z * v.z + v.w * v.w;
      colacc[i].x += v.x; colacc[i].y += v.y;
      colacc[i].z += v.z; colacc[i].w += v.w;
      __half2 lo = __floats2half2_rn(v.x, v.y);
      __half2 hi = __floats2half2_rn(v.z, v.w);
      uint2 pk;
      pk.x = *(uint32_t*)&lo;
      pk.y = *(uint32_t*)&hi;
      *(uint2*)(g_total + (size_t)row * KDIM + i * 128 + lane * 4) = pk;
    }
    #pragma unroll
    for (int o = 16; o; o >>= 1) sq += __shfl_xor_sync(0xffffffffu, sq, o);
    if (lane == 0) g_sq[row] = sq;
    wsumsq += (double)sq;
  }

  #pragma unroll
  for (int i = 0; i < 8; ++i) {
    int c = i * 128 + lane * 4;
    atomicAdd(&scol[c + 0], colacc[i].x);
    atomicAdd(&scol[c + 1], colacc[i].y);
    atomicAdd(&scol[c + 2], colacc[i].z);
    atomicAdd(&scol[c + 3], colacc[i].w);
  }
  if (lane == 0) ssq[wid] = wsumsq;
  __syncthreads();

  #pragma unroll
  for (int i = 0; i < KDIM / 256; ++i) {
    int c = tid + i * 256;
    g_colpart_blk[blockIdx.x][c] = scol[c];
  }
  if (tid == 0) {
    double t = 0.0;
    #pragma unroll
    for (int i = 0; i < 8; ++i) t += ssq[i];
    g_sumsq_blk[blockIdx.x] = t;
  }

  // ---- last-block bandwidth reduction ----
  __threadfence();
  __syncthreads();
  if (tid == 0) s_rank = atomicAdd(&g_prectr, 1u);
  __syncthreads();
  if (s_rank != PRE_BLOCKS - 1) return;

  double csq = 0.0;
  #pragma unroll
  for (int i = 0; i < KDIM / 256; ++i) {
    int c = tid + i * 256;
    float s = 0.f;
    for (int b = 0; b < PRE_BLOCKS; ++b) s += g_colpart_blk[b][c];
    csq += (double)s * (double)s;
  }
  sred[tid] = csq;
  __syncthreads();
  for (int s = 128; s; s >>= 1) {
    if (tid < s) sred[tid] += sred[tid + s];
    __syncthreads();
  }
  double colsq = sred[0];
  __syncthreads();
  sred[tid] = g_sumsq_blk[tid];
  __syncthreads();
  for (int s = 128; s; s >>= 1) {
    if (tid < s) sred[tid] += sred[tid + s];
    __syncthreads();
  }
  if (tid == 0) {
    double sumsq = sred[0];
    double sumL2 = 2.0 * (double)NTOT * sumsq - 2.0 * colsq;
    double bw = sumL2 / ((double)NTOT * (double)NTOT - (double)NTOT);
    bw *= 0.25;
    g_coef = (float)(-1.0 / (16.0 * bw));
    g_prectr = 0;   // reset for next graph replay
  }
}

// ---------------- Gram tile via f16 mma.sync + fused MMD epilogue + final ----------------
// SW128 swizzle on 128-byte rows: 16B-chunk index (bits [6:4]) XOR (row & 7).
__device__ __forceinline__ void load_stage(uint32_t sA, const __half* Ab,
                                           const __half* Bb, int t, int tid) {
  #pragma unroll
  for (int i = 0; i < 4; ++i) {
    int g   = tid + i * 256;
    int row = g >> 3;
    int cc  = g & 7;
    uint32_t soff = (uint32_t)row * 128u + (uint32_t)((cc ^ (row & 7)) << 4);
    const char* ga = (const char*)(Ab + (size_t)row * KDIM + t * CHUNK) + cc * 16;
    const char* gb = (const char*)(Bb + (size_t)row * KDIM + t * CHUNK) + cc * 16;
    cp16(sA + soff, ga);
    cp16(sA + TILE_BYTES + soff, gb);
  }
  cp_commit();
}

__global__ void __launch_bounds__(256, 3)
k_gemm(float* __restrict__ out) {
  extern __shared__ char dsm[];
  __shared__ double s_red[8];

  const int tid  = threadIdx.x;
  const int wid  = tid >> 5;
  const int lane = tid & 31;

  // triangular tile decode: bid = bp*(bp+1)/2 + bq
  int bid = blockIdx.x;
  int bp = (int)((sqrtf(8.0f * (float)bid + 1.0f) - 1.0f) * 0.5f);
  while ((bp + 1) * (bp + 2) / 2 <= bid) ++bp;
  while (bp * (bp + 1) / 2 > bid) --bp;
  int bq = bid - bp * (bp + 1) / 2;
  const int rowBase = bp * BM;
  const int colBase = bq * BM;

  const __half* Ab = g_total + (size_t)rowBase * KDIM;
  const __half* Bb = g_total + (size_t)colBase * KDIM;

  uint32_t sm0 = (smem_u32(dsm) + 127u) & ~127u;

  const int warp_m = wid & 1;    // 0..1 -> 64-row half
  const int warp_n = wid >> 1;   // 0..3 -> 32-col quarter
  const int lr  = lane & 7;
  const int sub = lane >> 3;

  // base LDSM addresses for kk=0 (stage-relative); kk advances via XOR chain
  const uint32_t a_kbit = (uint32_t)(sub >> 1);
  const uint32_t b_kbit = (uint32_t)(sub & 1);

  uint32_t a_base[4];
  #pragma unroll
  for (int mt = 0; mt < 4; ++mt) {
    int row = warp_m * 64 + mt * 16 + (sub & 1) * 8 + lr;
    a_base[mt] = (uint32_t)row * 128u + ((a_kbit ^ (uint32_t)(row & 7)) << 4);
  }
  uint32_t b_base[2];
  #pragma unroll
  for (int np = 0; np < 2; ++np) {
    int row = warp_n * 32 + np * 16 + (sub >> 1) * 8 + lr;
    b_base[np] = (uint32_t)row * 128u + ((b_kbit ^ (uint32_t)(row & 7)) << 4);
  }

  uint32_t acc[4][4][2];   // f16x2 accumulators
  #pragma unroll
  for (int i = 0; i < 4; ++i)
    #pragma unroll
    for (int j = 0; j < 4; ++j) { acc[i][j][0] = 0u; acc[i][j][1] = 0u; }

  load_stage(sm0 + 0 * STAGE_BYTES, Ab, Bb, 0, tid);
  load_stage(sm0 + 1 * STAGE_BYTES, Ab, Bb, 1, tid);

  int st = 0;
  for (int t = 0; t < NCHUNK; ++t) {
    if (t == NCHUNK - 1) cp_wait<0>(); else cp_wait<1>();
    __syncthreads();

    uint32_t sA = sm0 + st * STAGE_BYTES;
    uint32_t sB = sA + TILE_BYTES;

    // per-chunk LDSM addresses; kk advances by XOR 0x20/0x60/0x20
    // ((2kk|kbit)^rswz) differences are rswz-independent: 2,6,2 (<<4)
    uint32_t aaddr[4], baddr[2];
    #pragma unroll
    for (int mt = 0; mt < 4; ++mt) aaddr[mt] = sA + a_base[mt];
    #pragma unroll
    for (int np = 0; np < 2; ++np) baddr[np] = sB + b_base[np];

    #pragma unroll
    for (int kk = 0; kk < 4; ++kk) {
      uint32_t af[4][4];
      #pragma unroll
      for (int mt = 0; mt < 4; ++mt) ldsm4(af[mt], aaddr[mt]);
      uint32_t bf[2][4];
      #pragma unroll
      for (int np = 0; np < 2; ++np) ldsm4(bf[np], baddr[np]);

      if (kk < 3) {
        const uint32_t x = (kk == 1) ? 0x60u : 0x20u;
        #pragma unroll
        for (int mt = 0; mt < 4; ++mt) aaddr[mt] ^= x;
        #pragma unroll
        for (int np = 0; np < 2; ++np) baddr[np] ^= x;
      }

      #pragma unroll
      for (int mt = 0; mt < 4; ++mt) {
        #pragma unroll
        for (int nt = 0; nt < 4; ++nt)
          mma16816h(acc[mt][nt], af[mt], bf[nt >> 1][(nt & 1) * 2],
                    bf[nt >> 1][(nt & 1) * 2 + 1]);
      }
    }

    __syncthreads();
    if (t + NST < NCHUNK) load_stage(sm0 + st * STAGE_BYTES, Ab, Bb, t + NST, tid);
    st ^= 1;
  }

  // ---- fused epilogue ----
  const float coef = g_coef;
  const int tg = lane >> 2;
  const int tc = lane & 3;

  float sqp[4][2], sqq[4][2];
  #pragma unroll
  for (int mt = 0; mt < 4; ++mt) {
    int p0 = rowBase + warp_m * 64 + mt * 16 + tg;
    sqp[mt][0] = g_sq[p0];
    sqp[mt][1] = g_sq[p0 + 8];
  }
  #pragma unroll
  for (int nt = 0; nt < 4; ++nt) {
    int q0 = colBase + warp_n * 32 + nt * 8 + tc * 2;
    sqq[nt][0] = g_sq[q0];
    sqq[nt][1] = g_sq[q0 + 1];
  }

  float fsum = 0.f;
  #pragma unroll
  for (int mt = 0; mt < 4; ++mt) {
    #pragma unroll
    for (int nt = 0; nt < 4; ++nt) {
      #pragma unroll
      for (int h = 0; h < 2; ++h) {          // h=0: row tg, h=1: row tg+8
        float2 f = __half22float2(*(const __half2*)&acc[mt][nt][h]);
        float L2a = sqp[mt][h] + sqq[nt][0] - 2.0f * f.x;
        float L2b = sqp[mt][h] + sqq[nt][1] - 2.0f * f.y;
        float va = __expf(L2a * coef);
        float vb = __expf(L2b * coef);
        float va2 = va * va, va4 = va2 * va2, va8 = va4 * va4;
        float vb2 = vb * vb, vb4 = vb2 * vb2, vb8 = vb4 * vb4;
        fsum += va + va2 + va4 + va8 + va8 * va8;
        fsum += vb + vb2 + vb4 + vb8 + vb8 * vb8;
      }
    }
  }
  double d = (double)fsum;
  #pragma unroll
  for (int o = 16; o; o >>= 1) d += __shfl_xor_sync(0xffffffffu, d, o);
  if (lane == 0) s_red[wid] = d;
  __syncthreads();
  if (tid == 0) {
    double t = 0.0;
    #pragma unroll
    for (int i = 0; i < 8; ++i) t += s_red[i];
    double sgn = ((bp < NTILES / 2) == (bq < NTILES / 2)) ? 1.0 : -1.0;
    if (bp != bq) sgn *= 2.0;
    atomicAdd(&g_accum, sgn * t);

    // ---- fused finalization: last CTA writes the scalar output ----
    __threadfence();
    unsigned rank = atomicAdd(&g_donectr, 1u);
    if (rank == NBLOCKS - 1) {
      double total = atomicAdd(&g_accum, 0.0);   // ordered read after fence
      out[0] = (float)(total / ((double)NH * (double)NH));
      g_donectr = 0;   // reset for next graph replay
    }
  }
}

// ---------------- host launch ----------------
extern "C" void kernel_launch(void* const* d_in, const int* in_sizes, int n_in,
                              void* d_out, int out_size) {
  (void)in_sizes; (void)n_in; (void)out_size;
  const float* S = (const float*)d_in[0];
  const float* T = (const float*)d_in[1];

  cudaFuncSetAttribute(k_gemm, cudaFuncAttributeMaxDynamicSharedMemorySize, DYN_BYTES);

  k_pre<<<PRE_BLOCKS, 256>>>(S, T);
  k_gemm<<<NBLOCKS, 256, DYN_BYTES>>>((float*)d_out);
}

// round 15
// speedup vs baseline: 1.1061x; 1.0030x over previous
#include <cuda_runtime.h>
#include <cuda_fp16.h>
#include <math.h>
#include <stdint.h>

#define KDIM 1024
#define NH   4096
#define NTOT 8192
#define BM   128
#define NTILES (NTOT / BM)                       // 64
#define NBLOCKS (NTILES * (NTILES + 1) / 2)      // 2080
#define CHUNK 64                                 // K elements per stage (128 bytes)
#define NCHUNK (KDIM / CHUNK)                    // 16
#define NST 2
#define TILE_BYTES (BM * 128)                    // 16 KB
#define STAGE_BYTES (2 * TILE_BYTES)             // 32 KB
#define DYN_BYTES (NST * STAGE_BYTES + 256)      // ~64.25 KB

#define PRE_BLOCKS 256

// ---------------- device scratch ----------------
__device__ float  g_sq[NTOT];
__device__ float  g_colpart_blk[PRE_BLOCKS][KDIM];
__device__ double g_sumsq_blk[PRE_BLOCKS];
__device__ float  g_coef;       // -log2(e) / (16 * bandwidth)
__device__ double g_accum;
__device__ unsigned g_prectr = 0;    // self-resetting tickets
__device__ unsigned g_donectr = 0;
__device__ __half g_total[(size_t)NTOT * KDIM];  // f16 copy of [S;T]

// ---------------- PTX helpers (plain sm_80+ PTX) ----------------
__device__ __forceinline__ uint32_t smem_u32(const void* p) {
  uint32_t a;
  asm("{ .reg .u64 t; cvta.to.shared.u64 t, %1; cvt.u32.u64 %0, t; }" : "=r"(a) : "l"(p));
  return a;
}
__device__ __forceinline__ void cp16(uint32_t dst, const void* src) {
  asm volatile("cp.async.cg.shared.global [%0], [%1], 16;" :: "r"(dst), "l"(src) : "memory");
}
__device__ __forceinline__ void cp_commit() {
  asm volatile("cp.async.commit_group;" ::: "memory");
}
template <int N>
__device__ __forceinline__ void cp_wait() {
  asm volatile("cp.async.wait_group %0;" :: "n"(N) : "memory");
}
__device__ __forceinline__ void ldsm4(uint32_t* r, uint32_t addr) {
  asm volatile("ldmatrix.sync.aligned.m8n8.x4.shared.b16 {%0,%1,%2,%3}, [%4];"
               : "=r"(r[0]), "=r"(r[1]), "=r"(r[2]), "=r"(r[3]) : "r"(addr));
}
// f16 x f16 -> f16 accumulate (2 c-regs = 4 packed halves)
__device__ __forceinline__ void mma16816h(uint32_t* c, const uint32_t* a,
                                          uint32_t b0, uint32_t b1) {
  asm volatile(
    "mma.sync.aligned.m16n8k16.row.col.f16.f16.f16.f16 "
    "{%0,%1}, {%2,%3,%4,%5}, {%6,%7}, {%0,%1};"
    : "+r"(c[0]), "+r"(c[1])
    : "r"(a[0]), "r"(a[1]), "r"(a[2]), "r"(a[3]), "r"(b0), "r"(b1));
}

// ---------------- fused preprocessing + bandwidth (last block) ----------------
__global__ void __launch_bounds__(256)
k_pre(const float* __restrict__ S, const float* __restrict__ T) {
  __shared__ float  scol[KDIM];
  __shared__ double ssq[8];
  __shared__ double sred[256];
  __shared__ unsigned s_rank;

  const int tid  = threadIdx.x;
  const int wid  = tid >> 5;
  const int lane = tid & 31;

  if (blockIdx.x == 0 && tid == 0) g_accum = 0.0;

  #pragma unroll
  for (int i = 0; i < KDIM / 256; ++i) scol[tid + i * 256] = 0.f;
  __syncthreads();

  float4 colacc[8];
  #pragma unroll
  for (int i = 0; i < 8; ++i) colacc[i] = make_float4(0.f, 0.f, 0.f, 0.f);

  double wsumsq = 0.0;   // lane 0 accumulates full row norms

  #pragma unroll
  for (int r = 0; r < 4; ++r) {
    int row = blockIdx.x * 32 + wid * 4 + r;
    const float4* src = (const float4*)((row < NH) ? (S + (size_t)row * KDIM)
                                                   : (T + (size_t)(row - NH) * KDIM));
    float sq = 0.f;
    #pragma unroll
    for (int i = 0; i < 8; ++i) {
      float4 v = src[i * 32 + lane];
      sq += v.x * v.x + v.y * v.y + v.z * v.z + v.w * v.w;
      colacc[i].x += v.x; colacc[i].y += v.y;
      colacc[i].z += v.z; colacc[i].w += v.w;
      __half2 lo = __floats2half2_rn(v.x, v.y);
      __half2 hi = __floats2half2_rn(v.z, v.w);
      uint2 pk;
      pk.x = *(uint32_t*)&lo;
      pk.y = *(uint32_t*)&hi;
      *(uint2*)(g_total + (size_t)row * KDIM + i * 128 + lane * 4) = pk;
    }
    #pragma unroll
    for (int o = 16; o; o >>= 1) sq += __shfl_xor_sync(0xffffffffu, sq, o);
    if (lane == 0) g_sq[row] = sq;
    wsumsq += (double)sq;
  }

  #pragma unroll
  for (int i = 0; i < 8; ++i) {
    int c = i * 128 + lane * 4;
    atomicAdd(&scol[c + 0], colacc[i].x);
    atomicAdd(&scol[c + 1], colacc[i].y);
    atomicAdd(&scol[c + 2], colacc[i].z);
    atomicAdd(&scol[c + 3], colacc[i].w);
  }
  if (lane == 0) ssq[wid] = wsumsq;
  __syncthreads();

  #pragma unroll
  for (int i = 0; i < KDIM / 256; ++i) {
    int c = tid + i * 256;
    g_colpart_blk[blockIdx.x][c] = scol[c];
  }
  if (tid == 0) {
    double t = 0.0;
    #pragma unroll
    for (int i = 0; i < 8; ++i) t += ssq[i];
    g_sumsq_blk[blockIdx.x] = t;
  }

  // ---- last-block bandwidth reduction (vectorized: 4 contiguous cols/thread) ----
  __threadfence();
  __syncthreads();
  if (tid == 0) s_rank = atomicAdd(&g_prectr, 1u);
  __syncthreads();
  if (s_rank != PRE_BLOCKS - 1) return;

  float4 cs = make_float4(0.f, 0.f, 0.f, 0.f);
  {
    const float4* base = (const float4*)&g_colpart_blk[0][tid * 4];
    const int stride4 = KDIM / 4;               // float4s per slice row
    for (int b = 0; b < PRE_BLOCKS; ++b) {
      float4 v = base[(size_t)b * stride4];
      cs.x += v.x; cs.y += v.y; cs.z += v.z; cs.w += v.w;
    }
  }
  double csq = (double)cs.x * cs.x + (double)cs.y * cs.y
             + (double)cs.z * cs.z + (double)cs.w * cs.w;
  sred[tid] = csq;
  __syncthreads();
  for (int s = 128; s; s >>= 1) {
    if (tid < s) sred[tid] += sred[tid + s];
    __syncthreads();
  }
  double colsq = sred[0];
  __syncthreads();
  sred[tid] = g_sumsq_blk[tid];
  __syncthreads();
  for (int s = 128; s; s >>= 1) {
    if (tid < s) sred[tid] += sred[tid + s];
    __syncthreads();
  }
  if (tid == 0) {
    double sumsq = sred[0];
    double sumL2 = 2.0 * (double)NTOT * sumsq - 2.0 * colsq;
    double bw = sumL2 / ((double)NTOT * (double)NTOT - (double)NTOT);
    bw *= 0.25;
    g_coef = (float)(-1.4426950408889634 / (16.0 * bw));   // log2(e) folded in
    g_prectr = 0;   // reset for next graph replay
  }
}

// ---------------- Gram tile via f16 mma.sync + fused MMD epilogue + final ----------------
// SW128 swizzle on 128-byte rows: 16B-chunk index (bits [6:4]) XOR (row & 7).
__device__ __forceinline__ void load_stage(uint32_t sA, const __half* Ab,
                                           const __half* Bb, int t, int tid) {
  #pragma unroll
  for (int i = 0; i < 4; ++i) {
    int g   = tid + i * 256;
    int row = g >> 3;
    int cc  = g & 7;
    uint32_t soff = (uint32_t)row * 128u + (uint32_t)((cc ^ (row & 7)) << 4);
    const char* ga = (const char*)(Ab + (size_t)row * KDIM + t * CHUNK) + cc * 16;
    const char* gb = (const char*)(Bb + (size_t)row * KDIM + t * CHUNK) + cc * 16;
    cp16(sA + soff, ga);
    cp16(sA + TILE_BYTES + soff, gb);
  }
  cp_commit();
}

__global__ void __launch_bounds__(256, 3)
k_gemm(float* __restrict__ out) {
  extern __shared__ char dsm[];
  __shared__ double s_red[8];

  const int tid  = threadIdx.x;
  const int wid  = tid >> 5;
  const int lane = tid & 31;

  // triangular tile decode: bid = bp*(bp+1)/2 + bq
  int bid = blockIdx.x;
  int bp = (int)((sqrtf(8.0f * (float)bid + 1.0f) - 1.0f) * 0.5f);
  while ((bp + 1) * (bp + 2) / 2 <= bid) ++bp;
  while (bp * (bp + 1) / 2 > bid) --bp;
  int bq = bid - bp * (bp + 1) / 2;
  const int rowBase = bp * BM;
  const int colBase = bq * BM;

  const __half* Ab = g_total + (size_t)rowBase * KDIM;
  const __half* Bb = g_total + (size_t)colBase * KDIM;

  uint32_t sm0 = (smem_u32(dsm) + 127u) & ~127u;

  const int warp_m = wid & 1;    // 0..1 -> 64-row half
  const int warp_n = wid >> 1;   // 0..3 -> 32-col quarter
  const int lr  = lane & 7;
  const int sub = lane >> 3;

  const uint32_t a_kbit = (uint32_t)(sub >> 1);
  const uint32_t b_kbit = (uint32_t)(sub & 1);

  uint32_t a_base[4];
  #pragma unroll
  for (int mt = 0; mt < 4; ++mt) {
    int row = warp_m * 64 + mt * 16 + (sub & 1) * 8 + lr;
    a_base[mt] = (uint32_t)row * 128u + ((a_kbit ^ (uint32_t)(row & 7)) << 4);
  }
  uint32_t b_base[2];
  #pragma unroll
  for (int np = 0; np < 2; ++np) {
    int row = warp_n * 32 + np * 16 + (sub >> 1) * 8 + lr;
    b_base[np] = (uint32_t)row * 128u + ((b_kbit ^ (uint32_t)(row & 7)) << 4);
  }

  uint32_t acc[4][4][2];   // f16x2 accumulators
  #pragma unroll
  for (int i = 0; i < 4; ++i)
    #pragma unroll
    for (int j = 0; j < 4; ++j) { acc[i][j][0] = 0u; acc[i][j][1] = 0u; }

  load_stage(sm0 + 0 * STAGE_BYTES, Ab, Bb, 0, tid);
  load_stage(sm0 + 1 * STAGE_BYTES, Ab, Bb, 1, tid);

  int st = 0;
  for (int t = 0; t < NCHUNK; ++t) {
    if (t == NCHUNK - 1) cp_wait<0>(); else cp_wait<1>();
    __syncthreads();

    uint32_t sA = sm0 + st * STAGE_BYTES;
    uint32_t sB = sA + TILE_BYTES;

    uint32_t aaddr[4], baddr[2];
    #pragma unroll
    for (int mt = 0; mt < 4; ++mt) aaddr[mt] = sA + a_base[mt];
    #pragma unroll
    for (int np = 0; np < 2; ++np) baddr[np] = sB + b_base[np];

    #pragma unroll
    for (int kk = 0; kk < 4; ++kk) {
      uint32_t af[4][4];
      #pragma unroll
      for (int mt = 0; mt < 4; ++mt) ldsm4(af[mt], aaddr[mt]);
      uint32_t bf[2][4];
      #pragma unroll
      for (int np = 0; np < 2; ++np) ldsm4(bf[np], baddr[np]);

      if (kk < 3) {
        const uint32_t x = (kk == 1) ? 0x60u : 0x20u;
        #pragma unroll
        for (int mt = 0; mt < 4; ++mt) aaddr[mt] ^= x;
        #pragma unroll
        for (int np = 0; np < 2; ++np) baddr[np] ^= x;
      }

      #pragma unroll
      for (int mt = 0; mt < 4; ++mt) {
        #pragma unroll
        for (int nt = 0; nt < 4; ++nt)
          mma16816h(acc[mt][nt], af[mt], bf[nt >> 1][(nt & 1) * 2],
                    bf[nt >> 1][(nt & 1) * 2 + 1]);
      }
    }

    __syncthreads();
    if (t + NST < NCHUNK) load_stage(sm0 + st * STAGE_BYTES, Ab, Bb, t + NST, tid);
    st ^= 1;
  }

  // ---- fused epilogue (exp2-based: coef already includes log2e) ----
  const float coef = g_coef;
  const int tg = lane >> 2;
  const int tc = lane & 3;

  float sqp[4][2], sqq[4][2];
  #pragma unroll
  for (int mt = 0; mt < 4; ++mt) {
    int p0 = rowBase + warp_m * 64 + mt * 16 + tg;
    sqp[mt][0] = g_sq[p0];
    sqp[mt][1] = g_sq[p0 + 8];
  }
  #pragma unroll
  for (int nt = 0; nt < 4; ++nt) {
    int q0 = colBase + warp_n * 32 + nt * 8 + tc * 2;
    sqq[nt][0] = g_sq[q0];
    sqq[nt][1] = g_sq[q0 + 1];
  }

  float fsum = 0.f;
  #pragma unroll
  for (int mt = 0; mt < 4; ++mt) {
    #pragma unroll
    for (int nt = 0; nt < 4; ++nt) {
      #pragma unroll
      for (int h = 0; h < 2; ++h) {          // h=0: row tg, h=1: row tg+8
        float2 f = __half22float2(*(const __half2*)&acc[mt][nt][h]);
        float L2a = sqp[mt][h] + sqq[nt][0] - 2.0f * f.x;
        float L2b = sqp[mt][h] + sqq[nt][1] - 2.0f * f.y;
        float va = exp2f(L2a * coef);
        float vb = exp2f(L2b * coef);
        float va2 = va * va, va4 = va2 * va2, va8 = va4 * va4;
        float vb2 = vb * vb, vb4 = vb2 * vb2, vb8 = vb4 * vb4;
        fsum += va + va2 + va4 + va8 + va8 * va8;
        fsum += vb + vb2 + vb4 + vb8 + vb8 * vb8;
      }
    }
  }
  double d = (double)fsum;
  #pragma unroll
  for (int o = 16; o; o >>= 1) d += __shfl_xor_sync(0xffffffffu, d, o);
  if (lane == 0) s_red[wid] = d;
  __syncthreads();
  if (tid == 0) {
    double t = 0.0;
    #pragma unroll
    for (int i = 0; i < 8; ++i) t += s_red[i];
    double sgn = ((bp < NTILES / 2) == (bq < NTILES / 2)) ? 1.0 : -1.0;
    if (bp != bq) sgn *= 2.0;
    atomicAdd(&g_accum, sgn * t);

    // ---- fused finalization: last CTA writes the scalar output ----
    __threadfence();
    unsigned rank = atomicAdd(&g_donectr, 1u);
    if (rank == NBLOCKS - 1) {
      double total = atomicAdd(&g_accum, 0.0);   // ordered read after fence
      out[0] = (float)(total / ((double)NH * (double)NH));
      g_donectr = 0;   // reset for next graph replay
    }
  }
}

// ---------------- host launch ----------------
extern "C" void kernel_launch(void* const* d_in, const int* in_sizes, int n_in,
                              void* d_out, int out_size) {
  (void)in_sizes; (void)n_in; (void)out_size;
  const float* S = (const float*)d_in[0];
  const float* T = (const float*)d_in[1];

  cudaFuncSetAttribute(k_gemm, cudaFuncAttributeMaxDynamicSharedMemorySize, DYN_BYTES);

  k_pre<<<PRE_BLOCKS, 256>>>(S, T);
  k_gemm<<<NBLOCKS, 256, DYN_BYTES>>>((float*)d_out);
}

// round 16
// speedup vs baseline: 1.2065x; 1.0908x over previous
#include <cuda_runtime.h>
#include <cuda_fp16.h>
#include <math.h>
#include <stdint.h>

#define KDIM 1024
#define NH   4096
#define NTOT 8192
#define BM   128
#define NTILES (NTOT / BM)                       // 64
#define NBLOCKS (NTILES * (NTILES + 1) / 2)      // 2080
#define CHUNK 64                                 // K elements per stage (128 bytes)
#define NCHUNK (KDIM / CHUNK)                    // 16
#define NST 2
#define TILE_BYTES (BM * 128)                    // 16 KB
#define STAGE_BYTES (2 * TILE_BYTES)             // 32 KB
#define DYN_BYTES (NST * STAGE_BYTES + 256)      // ~64.25 KB

#define PRE_BLOCKS 256

// ---------------- device scratch ----------------
__device__ float  g_sq[NTOT];
__device__ float  g_colsum[KDIM];            // global column sums (atomic)
__device__ double g_sumsq;                   // global sum of row norms (atomic)
__device__ float  g_coef;                    // -log2(e) / (16 * bandwidth)
__device__ unsigned g_coef_ready = 0;
__device__ double g_accum;
__device__ unsigned g_donectr = 0;
__device__ __half g_total[(size_t)NTOT * KDIM];  // f16 copy of [S;T]

// ---------------- PTX helpers (plain sm_80+ PTX) ----------------
__device__ __forceinline__ uint32_t smem_u32(const void* p) {
  uint32_t a;
  asm("{ .reg .u64 t; cvta.to.shared.u64 t, %1; cvt.u32.u64 %0, t; }" : "=r"(a) : "l"(p));
  return a;
}
__device__ __forceinline__ void cp16(uint32_t dst, const void* src) {
  asm volatile("cp.async.cg.shared.global [%0], [%1], 16;" :: "r"(dst), "l"(src) : "memory");
}
__device__ __forceinline__ void cp_commit() {
  asm volatile("cp.async.commit_group;" ::: "memory");
}
template <int N>
__device__ __forceinline__ void cp_wait() {
  asm volatile("cp.async.wait_group %0;" :: "n"(N) : "memory");
}
__device__ __forceinline__ void ldsm4(uint32_t* r, uint32_t addr) {
  asm volatile("ldmatrix.sync.aligned.m8n8.x4.shared.b16 {%0,%1,%2,%3}, [%4];"
               : "=r"(r[0]), "=r"(r[1]), "=r"(r[2]), "=r"(r[3]) : "r"(addr));
}
// f16 x f16 -> f16 accumulate (2 c-regs = 4 packed halves)
__device__ __forceinline__ void mma16816h(uint32_t* c, const uint32_t* a,
                                          uint32_t b0, uint32_t b1) {
  asm volatile(
    "mma.sync.aligned.m16n8k16.row.col.f16.f16.f16.f16 "
    "{%0,%1}, {%2,%3,%4,%5}, {%6,%7}, {%0,%1};"
    : "+r"(c[0]), "+r"(c[1])
    : "r"(a[0]), "r"(a[1]), "r"(a[2]), "r"(a[3]), "r"(b0), "r"(b1));
}

// ---------------- fused preprocessing (no serialized tail) ----------------
__global__ void __launch_bounds__(256)
k_pre(const float* __restrict__ S, const float* __restrict__ T) {
  __shared__ float  scol[KDIM];
  __shared__ double ssq[8];

  const int tid  = threadIdx.x;
  const int wid  = tid >> 5;
  const int lane = tid & 31;

  if (blockIdx.x == 0 && tid == 0) g_accum = 0.0;

  #pragma unroll
  for (int i = 0; i < KDIM / 256; ++i) scol[tid + i * 256] = 0.f;
  __syncthreads();

  float4 colacc[8];
  #pragma unroll
  for (int i = 0; i < 8; ++i) colacc[i] = make_float4(0.f, 0.f, 0.f, 0.f);

  double wsumsq = 0.0;   // lane 0 accumulates full row norms

  #pragma unroll
  for (int r = 0; r < 4; ++r) {
    int row = blockIdx.x * 32 + wid * 4 + r;
    const float4* src = (const float4*)((row < NH) ? (S + (size_t)row * KDIM)
                                                   : (T + (size_t)(row - NH) * KDIM));
    float sq = 0.f;
    #pragma unroll
    for (int i = 0; i < 8; ++i) {
      float4 v = src[i * 32 + lane];
      sq += v.x * v.x + v.y * v.y + v.z * v.z + v.w * v.w;
      colacc[i].x += v.x; colacc[i].y += v.y;
      colacc[i].z += v.z; colacc[i].w += v.w;
      __half2 lo = __floats2half2_rn(v.x, v.y);
      __half2 hi = __floats2half2_rn(v.z, v.w);
      uint2 pk;
      pk.x = *(uint32_t*)&lo;
      pk.y = *(uint32_t*)&hi;
      *(uint2*)(g_total + (size_t)row * KDIM + i * 128 + lane * 4) = pk;
    }
    #pragma unroll
    for (int o = 16; o; o >>= 1) sq += __shfl_xor_sync(0xffffffffu, sq, o);
    if (lane == 0) g_sq[row] = sq;
    wsumsq += (double)sq;
  }

  #pragma unroll
  for (int i = 0; i < 8; ++i) {
    int c = i * 128 + lane * 4;
    atomicAdd(&scol[c + 0], colacc[i].x);
    atomicAdd(&scol[c + 1], colacc[i].y);
    atomicAdd(&scol[c + 2], colacc[i].z);
    atomicAdd(&scol[c + 3], colacc[i].w);
  }
  if (lane == 0) ssq[wid] = wsumsq;
  __syncthreads();

  // per-block partials -> global accumulators (256 adds/address: cheap)
  #pragma unroll
  for (int i = 0; i < KDIM / 256; ++i) {
    int c = tid + i * 256;
    atomicAdd(&g_colsum[c], scol[c]);
  }
  if (tid == 0) {
    double t = 0.0;
    #pragma unroll
    for (int i = 0; i < 8; ++i) t += ssq[i];
    atomicAdd(&g_sumsq, t);
  }
}

// ---------------- Gram tile via f16 mma.sync + fused MMD epilogue + final ----------------
// SW128 swizzle on 128-byte rows: 16B-chunk index (bits [6:4]) XOR (row & 7).
__device__ __forceinline__ void load_stage(uint32_t sA, const __half* Ab,
                                           const __half* Bb, int t, int tid) {
  #pragma unroll
  for (int i = 0; i < 4; ++i) {
    int g   = tid + i * 256;
    int row = g >> 3;
    int cc  = g & 7;
    uint32_t soff = (uint32_t)row * 128u + (uint32_t)((cc ^ (row & 7)) << 4);
    const char* ga = (const char*)(Ab + (size_t)row * KDIM + t * CHUNK) + cc * 16;
    const char* gb = (const char*)(Bb + (size_t)row * KDIM + t * CHUNK) + cc * 16;
    cp16(sA + soff, ga);
    cp16(sA + TILE_BYTES + soff, gb);
  }
  cp_commit();
}

__global__ void __launch_bounds__(256, 3)
k_gemm(float* __restrict__ out) {
  extern __shared__ char dsm[];
  __shared__ double s_red[8];
  __shared__ double s_cred[256];

  const int tid  = threadIdx.x;
  const int wid  = tid >> 5;
  const int lane = tid & 31;

  // ---- CTA 0: bandwidth reduction BEFORE its mainloop (off everyone's critical path) ----
  if (blockIdx.x == 0) {
    const float4* cs4 = (const float4*)&g_colsum[tid * 4];
    float4 v = *cs4;
    s_cred[tid] = (double)v.x * v.x + (double)v.y * v.y
                + (double)v.z * v.z + (double)v.w * v.w;
    // reset for next graph replay (value already captured)
    ((float4*)&g_colsum[tid * 4])[0] = make_float4(0.f, 0.f, 0.f, 0.f);
    __syncthreads();
    for (int s = 128; s; s >>= 1) {
      if (tid < s) s_cred[tid] += s_cred[tid + s];
      __syncthreads();
    }
    if (tid == 0) {
      double colsq = s_cred[0];
      double sumsq = g_sumsq;
      g_sumsq = 0.0;   // reset for next replay
      double sumL2 = 2.0 * (double)NTOT * sumsq - 2.0 * colsq;
      double bw = sumL2 / ((double)NTOT * (double)NTOT - (double)NTOT);
      bw *= 0.25;
      g_coef = (float)(-1.4426950408889634 / (16.0 * bw));   // log2(e) folded in
      __threadfence();
      atomicExch(&g_coef_ready, 1u);
    }
  }

  // triangular tile decode: bid = bp*(bp+1)/2 + bq
  int bid = blockIdx.x;
  int bp = (int)((sqrtf(8.0f * (float)bid + 1.0f) - 1.0f) * 0.5f);
  while ((bp + 1) * (bp + 2) / 2 <= bid) ++bp;
  while (bp * (bp + 1) / 2 > bid) --bp;
  int bq = bid - bp * (bp + 1) / 2;
  const int rowBase = bp * BM;
  const int colBase = bq * BM;

  const __half* Ab = g_total + (size_t)rowBase * KDIM;
  const __half* Bb = g_total + (size_t)colBase * KDIM;

  uint32_t sm0 = (smem_u32(dsm) + 127u) & ~127u;

  const int warp_m = wid & 1;    // 0..1 -> 64-row half
  const int warp_n = wid >> 1;   // 0..3 -> 32-col quarter
  const int lr  = lane & 7;
  const int sub = lane >> 3;

  const uint32_t a_kbit = (uint32_t)(sub >> 1);
  const uint32_t b_kbit = (uint32_t)(sub & 1);

  uint32_t a_base[4];
  #pragma unroll
  for (int mt = 0; mt < 4; ++mt) {
    int row = warp_m * 64 + mt * 16 + (sub & 1) * 8 + lr;
    a_base[mt] = (uint32_t)row * 128u + ((a_kbit ^ (uint32_t)(row & 7)) << 4);
  }
  uint32_t b_base[2];
  #pragma unroll
  for (int np = 0; np < 2; ++np) {
    int row = warp_n * 32 + np * 16 + (sub >> 1) * 8 + lr;
    b_base[np] = (uint32_t)row * 128u + ((b_kbit ^ (uint32_t)(row & 7)) << 4);
  }

  uint32_t acc[4][4][2];   // f16x2 accumulators
  #pragma unroll
  for (int i = 0; i < 4; ++i)
    #pragma unroll
    for (int j = 0; j < 4; ++j) { acc[i][j][0] = 0u; acc[i][j][1] = 0u; }

  load_stage(sm0 + 0 * STAGE_BYTES, Ab, Bb, 0, tid);
  load_stage(sm0 + 1 * STAGE_BYTES, Ab, Bb, 1, tid);

  int st = 0;
  for (int t = 0; t < NCHUNK; ++t) {
    if (t == NCHUNK - 1) cp_wait<0>(); else cp_wait<1>();
    __syncthreads();

    uint32_t sA = sm0 + st * STAGE_BYTES;
    uint32_t sB = sA + TILE_BYTES;

    uint32_t aaddr[4], baddr[2];
    #pragma unroll
    for (int mt = 0; mt < 4; ++mt) aaddr[mt] = sA + a_base[mt];
    #pragma unroll
    for (int np = 0; np < 2; ++np) baddr[np] = sB + b_base[np];

    #pragma unroll
    for (int kk = 0; kk < 4; ++kk) {
      uint32_t af[4][4];
      #pragma unroll
      for (int mt = 0; mt < 4; ++mt) ldsm4(af[mt], aaddr[mt]);
      uint32_t bf[2][4];
      #pragma unroll
      for (int np = 0; np < 2; ++np) ldsm4(bf[np], baddr[np]);

      if (kk < 3) {
        const uint32_t x = (kk == 1) ? 0x60u : 0x20u;
        #pragma unroll
        for (int mt = 0; mt < 4; ++mt) aaddr[mt] ^= x;
        #pragma unroll
        for (int np = 0; np < 2; ++np) baddr[np] ^= x;
      }

      #pragma unroll
      for (int mt = 0; mt < 4; ++mt) {
        #pragma unroll
        for (int nt = 0; nt < 4; ++nt)
          mma16816h(acc[mt][nt], af[mt], bf[nt >> 1][(nt & 1) * 2],
                    bf[nt >> 1][(nt & 1) * 2 + 1]);
      }
    }

    __syncthreads();
    if (t + NST < NCHUNK) load_stage(sm0 + st * STAGE_BYTES, Ab, Bb, t + NST, tid);
    st ^= 1;
  }

  // ---- wait for coef (set by CTA 0 ~2us in; epilogues start >=30us in) ----
  if (tid == 0) {
    while (atomicAdd(&g_coef_ready, 0u) == 0u) { }
    s_red[0] = 0.0;   // dummy store; sync below publishes visibility
  }
  __syncthreads();
  const float coef = g_coef;

  // ---- fused epilogue (exp2-based: coef already includes log2e) ----
  const int tg = lane >> 2;
  const int tc = lane & 3;

  float sqp[4][2], sqq[4][2];
  #pragma unroll
  for (int mt = 0; mt < 4; ++mt) {
    int p0 = rowBase + warp_m * 64 + mt * 16 + tg;
    sqp[mt][0] = g_sq[p0];
    sqp[mt][1] = g_sq[p0 + 8];
  }
  #pragma unroll
  for (int nt = 0; nt < 4; ++nt) {
    int q0 = colBase + warp_n * 32 + nt * 8 + tc * 2;
    sqq[nt][0] = g_sq[q0];
    sqq[nt][1] = g_sq[q0 + 1];
  }

  float fsum = 0.f;
  #pragma unroll
  for (int mt = 0; mt < 4; ++mt) {
    #pragma unroll
    for (int nt = 0; nt < 4; ++nt) {
      #pragma unroll
      for (int h = 0; h < 2; ++h) {          // h=0: row tg, h=1: row tg+8
        float2 f = __half22float2(*(const __half2*)&acc[mt][nt][h]);
        float L2a = sqp[mt][h] + sqq[nt][0] - 2.0f * f.x;
        float L2b = sqp[mt][h] + sqq[nt][1] - 2.0f * f.y;
        float va = exp2f(L2a * coef);
        float vb = exp2f(L2b * coef);
        float va2 = va * va, va4 = va2 * va2, va8 = va4 * va4;
        float vb2 = vb * vb, vb4 = vb2 * vb2, vb8 = vb4 * vb4;
        fsum += va + va2 + va4 + va8 + va8 * va8;
        fsum += vb + vb2 + vb4 + vb8 + vb8 * vb8;
      }
    }
  }
  double d = (double)fsum;
  #pragma unroll
  for (int o = 16; o; o >>= 1) d += __shfl_xor_sync(0xffffffffu, d, o);
  if (lane == 0) s_red[wid] = d;
  __syncthreads();
  if (tid == 0) {
    double t = 0.0;
    #pragma unroll
    for (int i = 0; i < 8; ++i) t += s_red[i];
    double sgn = ((bp < NTILES / 2) == (bq < NTILES / 2)) ? 1.0 : -1.0;
    if (bp != bq) sgn *= 2.0;
    atomicAdd(&g_accum, sgn * t);

    // ---- fused finalization: last CTA writes the scalar output ----
    __threadfence();
    unsigned rank = atomicAdd(&g_donectr, 1u);
    if (rank == NBLOCKS - 1) {
      double total = atomicAdd(&g_accum, 0.0);   // ordered read after fence
      out[0] = (float)(total / ((double)NH * (double)NH));
      g_donectr = 0;       // reset for next graph replay
      g_coef_ready = 0;
    }
  }
}

// ---------------- host launch ----------------
extern "C" void kernel_launch(void* const* d_in, const int* in_sizes, int n_in,
                              void* d_out, int out_size) {
  (void)in_sizes; (void)n_in; (void)out_size;
  const float* S = (const float*)d_in[0];
  const float* T = (const float*)d_in[1];

  cudaFuncSetAttribute(k_gemm, cudaFuncAttributeMaxDynamicSharedMemorySize, DYN_BYTES);

  k_pre<<<PRE_BLOCKS, 256>>>(S, T);
  k_gemm<<<NBLOCKS, 256, DYN_BYTES>>>((float*)d_out);
}